// round 16
// baseline (speedup 1.0000x reference)
#include <cuda_runtime.h>
#include <cuda_bf16.h>
#include <mma.h>
#include <math.h>

using namespace nvcuda;

#define BB 1024
#define TT 128
#define NN 256
#define HH 128
#define GG 512
#define BM 7
#define NBLK 147
#define AP 264          // xproj A pitch (bf16)
#define BP 72           // xproj B pitch (bf16)
#define APL 136         // lstm A pitch (bf16)
#define ACW 68          // lstm per-warp acc pitch (fp32), 4 tiles of 16 cols

typedef unsigned long long ull;
typedef unsigned int u32;

// ---------------- scratch ----------------------------------------------------
__device__ float  g_bias[GG];
__device__ float  g_xproj[(size_t)BB * TT * GG];
__device__ __nv_bfloat16 g_wbf[GG * NN];    // [j][k] bf16(w_ih)
__device__ __nv_bfloat16 g_whhbf[GG * HH];  // [j][k] bf16(w_hh)

// ---------------- helpers ----------------------------------------------------
__device__ __forceinline__ float fsig(float x) {
    float e = __expf(-x); return __fdividef(1.0f, 1.0f + e);
}
__device__ __forceinline__ float ftanh(float x) {
    float e = __expf(2.0f * x); return 1.0f - __fdividef(2.0f, e + 1.0f);
}
__device__ __forceinline__ ull pack_bf4(float a, float b, float c, float d) {
    __nv_bfloat162 p01 = __halves2bfloat162(__float2bfloat16_rn(a), __float2bfloat16_rn(b));
    __nv_bfloat162 p23 = __halves2bfloat162(__float2bfloat16_rn(c), __float2bfloat16_rn(d));
    return (ull)(*(u32*)&p01) | ((ull)(*(u32*)&p23) << 32);
}
__device__ __forceinline__ ull pack2f(float lo, float hi) {
    ull r; asm("mov.b64 %0, {%1,%2};" : "=l"(r) : "f"(lo), "f"(hi)); return r;
}
__device__ __forceinline__ void fma2(ull& d, ull a, ull b) {
    asm("fma.rn.f32x2 %0, %1, %2, %0;" : "+l"(d) : "l"(a), "l"(b));
}
__device__ __forceinline__ float2 unpack2(ull v) {
    float2 f; asm("mov.b64 {%0,%1}, %2;" : "=f"(f.x), "=f"(f.y) : "l"(v)); return f;
}

// ---------------------------------------------------------------------------
// Setup
// ---------------------------------------------------------------------------
__global__ void setup_kernel(const float* __restrict__ w_ih,
                             const float* __restrict__ w_hh,
                             const float* __restrict__ b_ih,
                             const float* __restrict__ b_hh) {
    int idx = blockIdx.x * blockDim.x + threadIdx.x;
    int stride = gridDim.x * blockDim.x;
    if (idx < GG) g_bias[idx] = b_ih[idx] + b_hh[idx];
    for (int i = idx; i < GG * NN; i += stride)
        g_wbf[i] = __float2bfloat16_rn(w_ih[i]);
    for (int i = idx; i < GG * HH; i += stride)
        g_whhbf[i] = __float2bfloat16_rn(w_hh[i]);
}

// ---------------------------------------------------------------------------
// Fused attention + xproj (R14 version: vectorized feat pass). One CTA per b.
// ---------------------------------------------------------------------------
#define SMX_A   0
#define SMX_B   (128 * AP * 2)
#define SMX_SA  (SMX_B + 2 * 128 * BP * 2)
#define SMX_RED (SMX_SA + NN * 4)
#define SMX_WX  (SMX_RED + 256 * 4)
#define SMX_P   (SMX_WX + TT * 4)
#define XP_SMEM (SMX_P + 4 * 256 * 4)

__global__ __launch_bounds__(256, 2)
void fused_attn_xproj_kernel(const float* __restrict__ x,
                             const float* __restrict__ attn_w,
                             const float* __restrict__ attn_b,
                             float* __restrict__ out_attn,
                             float* __restrict__ xp) {
    extern __shared__ char smem[];
    __nv_bfloat16* As = (__nv_bfloat16*)(smem + SMX_A);
    __nv_bfloat16* Bs = (__nv_bfloat16*)(smem + SMX_B);
    float* s_a   = (float*)(smem + SMX_SA);
    float* s_red = (float*)(smem + SMX_RED);
    float* s_wx  = (float*)(smem + SMX_WX);
    float* s_p   = (float*)(smem + SMX_P);

    int b = blockIdx.x;
    int tid = threadIdx.x;
    int wid = tid >> 5;
    int n = tid;
    const float* xb = x + (size_t)b * TT * NN;

    if (tid < TT) s_wx[tid] = attn_w[2 * HH + tid];
    __syncthreads();

    {
        int fg = tid >> 6;
        int q4 = (tid & 63) * 4;
        float4 p = make_float4(0.f, 0.f, 0.f, 0.f);
        const float* xg = xb + (size_t)(fg * 32) * NN + q4;
#pragma unroll 8
        for (int tt = 0; tt < 32; tt++) {
            float4 xv = *(const float4*)&xg[(size_t)tt * NN];
            float w = s_wx[fg * 32 + tt];
            p.x = fmaf(xv.x, w, p.x);
            p.y = fmaf(xv.y, w, p.y);
            p.z = fmaf(xv.z, w, p.z);
            p.w = fmaf(xv.w, w, p.w);
        }
        *(float4*)&s_p[fg * 256 + q4] = p;
    }
    __syncthreads();
    float feat = attn_b[0] + s_p[n] + s_p[256 + n] + s_p[512 + n] + s_p[768 + n];

    s_red[n] = feat;
    __syncthreads();
#pragma unroll
    for (int s = 128; s > 0; s >>= 1) {
        if (n < s) s_red[n] = fmaxf(s_red[n], s_red[n + s]);
        __syncthreads();
    }
    float m = s_red[0];
    __syncthreads();
    float e = expf(feat - m);
    s_red[n] = e;
    __syncthreads();
#pragma unroll
    for (int s = 128; s > 0; s >>= 1) {
        if (n < s) s_red[n] += s_red[n + s];
        __syncthreads();
    }
    s_a[n] = e / s_red[0];
    __syncthreads();

    {
        float* ob = out_attn + (size_t)b * TT * NN;
#pragma unroll 4
        for (int i = tid; i < TT * NN / 4; i += 256) {
            int t = i >> 6, n4 = (i & 63) * 4;
            *(float4*)&ob[(size_t)t * NN + n4] = *(const float4*)&s_a[n4];
        }
    }

#pragma unroll
    for (int it = 0; it < 16; it++) {
        int seg = tid + 256 * it;
        int t = seg >> 5;
        int k8 = (seg & 31) * 8;
        float4 x0 = *(const float4*)&xb[(size_t)t * NN + k8];
        float4 x1 = *(const float4*)&xb[(size_t)t * NN + k8 + 4];
        float4 a0 = *(const float4*)&s_a[k8];
        float4 a1 = *(const float4*)&s_a[k8 + 4];
        float v[8] = {x0.x * a0.x, x0.y * a0.y, x0.z * a0.z, x0.w * a0.w,
                      x1.x * a1.x, x1.y * a1.y, x1.z * a1.z, x1.w * a1.w};
        u32 hw[4];
#pragma unroll
        for (int p = 0; p < 4; p++) {
            __nv_bfloat162 hp = __halves2bfloat162(
                __float2bfloat16_rn(v[2 * p]), __float2bfloat16_rn(v[2 * p + 1]));
            hw[p] = *(u32*)&hp;
        }
        *(uint4*)&As[t * AP + k8] = make_uint4(hw[0], hw[1], hw[2], hw[3]);
    }

    int jseg = tid >> 3, kl8 = (tid & 7) * 8;
    uint4 rb[4];
#pragma unroll
    for (int it = 0; it < 4; it++) {
        int j = jseg + 32 * it;
        rb[it] = *(const uint4*)&g_wbf[(size_t)j * NN + kl8];
    }

    int m0 = (wid >> 1) * 32;
    int n0 = (wid & 1) * 64;

    __syncthreads();

    int cc = 0;
    for (int jt = 0; jt < 4; jt++) {
        wmma::fragment<wmma::accumulator, 16, 16, 16, float> acc[2][4];
#pragma unroll
        for (int i = 0; i < 2; i++)
#pragma unroll
            for (int nn = 0; nn < 4; nn++) wmma::fill_fragment(acc[i][nn], 0.0f);

        for (int c = 0; c < 4; c++, cc++) {
            __nv_bfloat16* Bc = Bs + (cc & 1) * 128 * BP;
#pragma unroll
            for (int it = 0; it < 4; it++) {
                int j = jseg + 32 * it;
                *(uint4*)&Bc[j * BP + kl8] = rb[it];
            }
            __syncthreads();

            if (cc < 15) {
                int njt = (cc + 1) >> 2, nc = (cc + 1) & 3;
#pragma unroll
                for (int it = 0; it < 4; it++) {
                    int j = jseg + 32 * it;
                    rb[it] = *(const uint4*)
                        &g_wbf[(size_t)(njt * 128 + j) * NN + nc * 64 + kl8];
                }
            }

            int a_off = c * 64;
#pragma unroll
            for (int ks = 0; ks < 4; ks++) {
                wmma::fragment<wmma::matrix_a, 16, 16, 16, __nv_bfloat16, wmma::row_major> af[2];
#pragma unroll
                for (int i = 0; i < 2; i++)
                    wmma::load_matrix_sync(af[i], &As[(m0 + i * 16) * AP + a_off + ks * 16], AP);
#pragma unroll
                for (int nn = 0; nn < 4; nn++) {
                    wmma::fragment<wmma::matrix_b, 16, 16, 16, __nv_bfloat16, wmma::col_major> bf;
                    wmma::load_matrix_sync(bf, &Bc[(n0 + nn * 16) * BP + ks * 16], BP);
                    wmma::mma_sync(acc[0][nn], af[0], bf, acc[0][nn]);
                    wmma::mma_sync(acc[1][nn], af[1], bf, acc[1][nn]);
                }
            }
        }

#pragma unroll
        for (int i = 0; i < 2; i++)
#pragma unroll
            for (int nn = 0; nn < 4; nn++)
                wmma::store_matrix_sync(
                    xp + ((size_t)b * TT + m0 + i * 16) * GG + jt * 128 + n0 + nn * 16,
                    acc[i][nn], GG, wmma::mem_row_major);
    }
}

// ---------------------------------------------------------------------------
// Recurrent LSTM, dual-pipe (HMMA + FFMA2 concurrently), K-split:
//  warps 0-7  (HMMA): k in [0,64), hi/lo bf16 rows, 16 wmma/step, all 4 gates
//  warps 8-15 (FFMA): k in [64,128) in EXACT fp32, 2 cols/thread, f32x2;
//                     folds bias + xproj into its partial (s_gf)
//  epilogue (warps 0-7, lanes<28): gate = acc_hi + acc_lo + s_gf
//  Warp-specialized branches keep register liveness disjoint.
// ---------------------------------------------------------------------------
#define LSM_AS   0                              // 2 * 16*APL bf16 = 8704
#define LSM_ACC  8704                           // 8 * 16*ACW f32 = 34816
#define LSM_GF   43520                          // 7*512 f32 = 14336
#define LSM_HF   57856                          // 2 * 7*128 f32 = 7168
#define LSM_WS   65024                          // 8*512 float4 = 65536
#define LSTM_SMEM 130560

__global__ __launch_bounds__(512, 1)
void lstm_hybrid_kernel(const float* __restrict__ xp,
                        const float* __restrict__ h0,
                        const float* __restrict__ c0,
                        const float* __restrict__ w_hh,
                        float* __restrict__ out_enc) {
    extern __shared__ char smem[];
    __nv_bfloat16* As  = (__nv_bfloat16*)(smem + LSM_AS);   // [2][16*APL]
    float*  s_acc = (float*)(smem + LSM_ACC);               // [8][16*ACW]
    float*  s_gf  = (float*)(smem + LSM_GF);                // [7][512]
    float*  s_hf  = (float*)(smem + LSM_HF);                // [2][7*128]
    float4* ws4   = (float4*)(smem + LSM_WS);               // [8][512]

    int tid = threadIdx.x;
    int wid = tid >> 5;
    int lane = tid & 31;
    int b0 = blockIdx.x * BM;

    // fill ws4 (w_hh fp32, k in [96,128)) and zero A pad rows
    for (int i = tid; i < 8 * 512; i += 512) {
        int k4 = i >> 9, j = i & 511;
        ws4[i] = *(const float4*)&w_hh[j * HH + 96 + 4 * k4];
    }
    for (int i = tid; i < 2 * (APL / 4); i += 512) {
        int row = (i < APL / 4) ? 7 : 15;
        int col = (i % (APL / 4)) * 4;
        *(ull*)&As[row * APL + col] = 0ULL;
        *(ull*)&As[16 * APL + row * APL + col] = 0ULL;
    }

    if (wid < 8) {
        // =================== HMMA + epilogue warps ===================
        // B frags: 4 gates x 4 ksteps (k < 64), cols wid*16..+16
        wmma::fragment<wmma::matrix_b, 16, 16, 16, __nv_bfloat16, wmma::col_major> bf[4][4];
#pragma unroll
        for (int g = 0; g < 4; g++)
#pragma unroll
            for (int ks = 0; ks < 4; ks++)
                wmma::load_matrix_sync(bf[g][ks],
                    g_whhbf + (size_t)(g * 128 + wid * 16) * HH + ks * 16, HH);

        const int er = lane >> 2;
        const int kq = (lane & 3) * 4;
        const int kk = wid * 16 + kq;
        const bool eact = lane < 28;
        const bool ewr  = eact && (b0 + er < BB);

        float c_reg[4] = {0.f, 0.f, 0.f, 0.f};
        if (eact) {
            float4 hv = make_float4(0.f, 0.f, 0.f, 0.f);
            if (ewr) {
                hv = *(const float4*)&h0[(size_t)(b0 + er) * HH + kk];
                float4 cv = *(const float4*)&c0[(size_t)(b0 + er) * HH + kk];
                c_reg[0] = cv.x; c_reg[1] = cv.y; c_reg[2] = cv.z; c_reg[3] = cv.w;
            }
            ull hi = pack_bf4(hv.x, hv.y, hv.z, hv.w);
            float r0 = hv.x - __bfloat162float(__float2bfloat16_rn(hv.x));
            float r1 = hv.y - __bfloat162float(__float2bfloat16_rn(hv.y));
            float r2 = hv.z - __bfloat162float(__float2bfloat16_rn(hv.z));
            float r3 = hv.w - __bfloat162float(__float2bfloat16_rn(hv.w));
            ull lo = pack_bf4(r0, r1, r2, r3);
            *(ull*)&As[er * APL + kk]       = hi;
            *(ull*)&As[(er + 8) * APL + kk] = lo;
            *(float4*)&s_hf[er * HH + kk]   = hv;
        }
        float* accw = &s_acc[wid * 16 * ACW];

        __syncthreads();   // A

        for (int t = 0; t < TT; t++) {
            int cur = t & 1, nxt = cur ^ 1;

            // MMA: 4 gate tiles, K = 64 (4 ksteps)
            wmma::fragment<wmma::accumulator, 16, 16, 16, float> acc[4];
#pragma unroll
            for (int g = 0; g < 4; g++) wmma::fill_fragment(acc[g], 0.0f);
#pragma unroll
            for (int ks = 0; ks < 4; ks++) {
                wmma::fragment<wmma::matrix_a, 16, 16, 16, __nv_bfloat16, wmma::row_major> af;
                wmma::load_matrix_sync(af, &As[cur * 16 * APL + ks * 16], APL);
#pragma unroll
                for (int g = 0; g < 4; g++)
                    wmma::mma_sync(acc[g], af, bf[g][ks], acc[g]);
            }
#pragma unroll
            for (int g = 0; g < 4; g++)
                wmma::store_matrix_sync(&accw[g * 16], acc[g], ACW, wmma::mem_row_major);
            __syncthreads();   // B

            if (eact) {
                float gate[4][4];
#pragma unroll
                for (int g = 0; g < 4; g++) {
                    float4 ahi = *(const float4*)&accw[er * ACW + g * 16 + kq];
                    float4 alo = *(const float4*)&accw[(er + 8) * ACW + g * 16 + kq];
                    float4 gf  = *(const float4*)&s_gf[er * GG + g * 128 + kk];
                    gate[g][0] = ahi.x + alo.x + gf.x;
                    gate[g][1] = ahi.y + alo.y + gf.y;
                    gate[g][2] = ahi.z + alo.z + gf.z;
                    gate[g][3] = ahi.w + alo.w + gf.w;
                }
                float hn[4];
#pragma unroll
                for (int l = 0; l < 4; l++) {
                    float iv = fsig(gate[0][l]);
                    float fv = fsig(gate[1][l]);
                    float gv = ftanh(gate[2][l]);
                    float ov = fsig(gate[3][l]);
                    c_reg[l] = fmaf(fv, c_reg[l], iv * gv);
                    hn[l] = ov * ftanh(c_reg[l]);
                }
                ull hi = pack_bf4(hn[0], hn[1], hn[2], hn[3]);
                float r0 = hn[0] - __bfloat162float(__float2bfloat16_rn(hn[0]));
                float r1 = hn[1] - __bfloat162float(__float2bfloat16_rn(hn[1]));
                float r2 = hn[2] - __bfloat162float(__float2bfloat16_rn(hn[2]));
                float r3 = hn[3] - __bfloat162float(__float2bfloat16_rn(hn[3]));
                ull lo = pack_bf4(r0, r1, r2, r3);
                *(ull*)&As[nxt * 16 * APL + er * APL + kk]       = hi;
                *(ull*)&As[nxt * 16 * APL + (er + 8) * APL + kk] = lo;
                *(float4*)&s_hf[nxt * BM * HH + er * HH + kk] =
                    make_float4(hn[0], hn[1], hn[2], hn[3]);
                if (ewr)
                    *(float4*)(out_enc + ((size_t)(b0 + er) * TT + t) * HH + kk) =
                        make_float4(hn[0], hn[1], hn[2], hn[3]);
            }
            __syncthreads();   // C
        }
    } else {
        // =================== FFMA warps: k in [64,128), fp32 exact ===========
        int ft = tid - 256;            // 0..255
        int j0 = ft, j1 = ft + 256;

        // weights k in [64,96) in registers (16 k2 per col)
        ull wr0[16], wr1[16];
#pragma unroll
        for (int k2 = 0; k2 < 16; k2++) {
            wr0[k2] = *(const ull*)&w_hh[j0 * HH + 64 + 2 * k2];
            wr1[k2] = *(const ull*)&w_hh[j1 * HH + 64 + 2 * k2];
        }
        float bias0 = g_bias[j0], bias1 = g_bias[j1];

        int brow[BM];
#pragma unroll
        for (int r = 0; r < BM; r++) {
            int b = b0 + r; if (b > BB - 1) b = BB - 1;
            brow[r] = b;
        }

        __syncthreads();   // A

        for (int t = 0; t < TT; t++) {
            int cur = t & 1;
            const float* hf = &s_hf[cur * BM * HH];

            // acc init = bias + xproj (folded); lane layout (val, 0)
            ull acc0[BM], acc1[BM];
#pragma unroll
            for (int r = 0; r < BM; r++) {
                float x0 = xp[((size_t)brow[r] * TT + t) * GG + j0];
                float x1 = xp[((size_t)brow[r] * TT + t) * GG + j1];
                acc0[r] = pack2f(bias0 + x0, 0.f);
                acc1[r] = pack2f(bias1 + x1, 0.f);
            }

            // k in [64,96): register weights
#pragma unroll
            for (int k4 = 0; k4 < 8; k4++) {
#pragma unroll
                for (int r = 0; r < BM; r++) {
                    ulonglong2 hp = *(const ulonglong2*)&hf[r * HH + 64 + 4 * k4];
                    fma2(acc0[r], hp.x, wr0[2 * k4]); fma2(acc0[r], hp.y, wr0[2 * k4 + 1]);
                    fma2(acc1[r], hp.x, wr1[2 * k4]); fma2(acc1[r], hp.y, wr1[2 * k4 + 1]);
                }
            }
            // k in [96,128): smem weights
#pragma unroll
            for (int k4 = 0; k4 < 8; k4++) {
                ulonglong2 w0 = *(const ulonglong2*)&ws4[k4 * 512 + j0];
                ulonglong2 w1 = *(const ulonglong2*)&ws4[k4 * 512 + j1];
#pragma unroll
                for (int r = 0; r < BM; r++) {
                    ulonglong2 hp = *(const ulonglong2*)&hf[r * HH + 96 + 4 * k4];
                    fma2(acc0[r], hp.x, w0.x); fma2(acc0[r], hp.y, w0.y);
                    fma2(acc1[r], hp.x, w1.x); fma2(acc1[r], hp.y, w1.y);
                }
            }

#pragma unroll
            for (int r = 0; r < BM; r++) {
                float2 p0 = unpack2(acc0[r]);
                float2 p1 = unpack2(acc1[r]);
                s_gf[r * GG + j0] = p0.x + p0.y;
                s_gf[r * GG + j1] = p1.x + p1.y;
            }
            __syncthreads();   // B
            __syncthreads();   // C
        }
    }
}

// ---------------------------------------------------------------------------
// Launch
// ---------------------------------------------------------------------------
extern "C" void kernel_launch(void* const* d_in, const int* in_sizes, int n_in,
                              void* d_out, int out_size) {
    const float* x      = (const float*)d_in[0];
    const float* attn_w = (const float*)d_in[1];
    const float* attn_b = (const float*)d_in[2];
    const float* w_ih   = (const float*)d_in[3];
    const float* w_hh   = (const float*)d_in[4];
    const float* b_ih   = (const float*)d_in[5];
    const float* b_hh   = (const float*)d_in[6];
    const float* h0     = (const float*)d_in[7];
    const float* c0     = (const float*)d_in[8];

    float* out      = (float*)d_out;
    float* out_attn = out;
    float* out_enc  = out + (size_t)BB * TT * NN;

    float* xproj;
    cudaGetSymbolAddress((void**)&xproj, g_xproj);

    cudaFuncSetAttribute(fused_attn_xproj_kernel,
                         cudaFuncAttributeMaxDynamicSharedMemorySize, XP_SMEM);
    cudaFuncSetAttribute(lstm_hybrid_kernel,
                         cudaFuncAttributeMaxDynamicSharedMemorySize, LSTM_SMEM);

    setup_kernel<<<192, 256>>>(w_ih, w_hh, b_ih, b_hh);
    fused_attn_xproj_kernel<<<BB, 256, XP_SMEM>>>(x, attn_w, attn_b, out_attn, xproj);
    lstm_hybrid_kernel<<<NBLK, 512, LSTM_SMEM>>>(xproj, h0, c0, w_hh, out_enc);
}

// round 17
// speedup vs baseline: 1.6642x; 1.6642x over previous
#include <cuda_runtime.h>
#include <cuda_fp16.h>
#include <mma.h>
#include <math.h>

using namespace nvcuda;

#define BB 1024
#define TT 128
#define NN 256
#define HH 128
#define GG 512
#define BM 7
#define NBLK 147
#define AP 264          // xproj A pitch (fp16)
#define BP 72           // xproj B pitch (fp16)
#define APL 136         // lstm A pitch (fp16)
#define ACW 68          // lstm per-warp acc pitch (fp32)

typedef unsigned long long ull;
typedef unsigned int u32;

// ---------------- scratch ----------------------------------------------------
__device__ float  g_bias[GG];
__device__ float  g_xproj[(size_t)BB * TT * GG];
__device__ __half g_wh[GG * NN];    // [j][k] fp16(w_ih)
__device__ __half g_whhh[GG * HH];  // [j][k] fp16(w_hh)

// ---------------- helpers ----------------------------------------------------
__device__ __forceinline__ float fsig(float x) {
    float e = __expf(-x); return __fdividef(1.0f, 1.0f + e);
}
__device__ __forceinline__ float ftanh(float x) {
    float e = __expf(2.0f * x); return 1.0f - __fdividef(2.0f, e + 1.0f);
}
__device__ __forceinline__ ull pack_h4(float a, float b, float c, float d) {
    __half2 p01 = __halves2half2(__float2half_rn(a), __float2half_rn(b));
    __half2 p23 = __halves2half2(__float2half_rn(c), __float2half_rn(d));
    return (ull)(*(u32*)&p01) | ((ull)(*(u32*)&p23) << 32);
}

// ---------------------------------------------------------------------------
// Setup
// ---------------------------------------------------------------------------
__global__ void setup_kernel(const float* __restrict__ w_ih,
                             const float* __restrict__ w_hh,
                             const float* __restrict__ b_ih,
                             const float* __restrict__ b_hh) {
    int idx = blockIdx.x * blockDim.x + threadIdx.x;
    int stride = gridDim.x * blockDim.x;
    if (idx < GG) g_bias[idx] = b_ih[idx] + b_hh[idx];
    for (int i = idx; i < GG * NN; i += stride)
        g_wh[i] = __float2half_rn(w_ih[i]);
    for (int i = idx; i < GG * HH; i += stride)
        g_whhh[i] = __float2half_rn(w_hh[i]);
}

// ---------------------------------------------------------------------------
// Fused attention + xproj (R13 structure + R14 vectorized feat), fp16 MMA.
// ---------------------------------------------------------------------------
#define SMX_A   0
#define SMX_B   (128 * AP * 2)
#define SMX_SA  (SMX_B + 2 * 128 * BP * 2)
#define SMX_RED (SMX_SA + NN * 4)
#define SMX_WX  (SMX_RED + 256 * 4)
#define SMX_P   (SMX_WX + TT * 4)
#define XP_SMEM (SMX_P + 4 * 256 * 4)

__global__ __launch_bounds__(256, 2)
void fused_attn_xproj_kernel(const float* __restrict__ x,
                             const float* __restrict__ attn_w,
                             const float* __restrict__ attn_b,
                             float* __restrict__ out_attn,
                             float* __restrict__ xp) {
    extern __shared__ char smem[];
    __half* As = (__half*)(smem + SMX_A);
    __half* Bs = (__half*)(smem + SMX_B);
    float* s_a   = (float*)(smem + SMX_SA);
    float* s_red = (float*)(smem + SMX_RED);
    float* s_wx  = (float*)(smem + SMX_WX);
    float* s_p   = (float*)(smem + SMX_P);

    int b = blockIdx.x;
    int tid = threadIdx.x;
    int wid = tid >> 5;
    int n = tid;
    const float* xb = x + (size_t)b * TT * NN;

    if (tid < TT) s_wx[tid] = attn_w[2 * HH + tid];
    __syncthreads();

    // feat partials: vectorized, 4-way t-split
    {
        int fg = tid >> 6;
        int q4 = (tid & 63) * 4;
        float4 p = make_float4(0.f, 0.f, 0.f, 0.f);
        const float* xg = xb + (size_t)(fg * 32) * NN + q4;
#pragma unroll 8
        for (int tt = 0; tt < 32; tt++) {
            float4 xv = *(const float4*)&xg[(size_t)tt * NN];
            float w = s_wx[fg * 32 + tt];
            p.x = fmaf(xv.x, w, p.x);
            p.y = fmaf(xv.y, w, p.y);
            p.z = fmaf(xv.z, w, p.z);
            p.w = fmaf(xv.w, w, p.w);
        }
        *(float4*)&s_p[fg * 256 + q4] = p;
    }
    __syncthreads();
    float feat = attn_b[0] + s_p[n] + s_p[256 + n] + s_p[512 + n] + s_p[768 + n];

    s_red[n] = feat;
    __syncthreads();
#pragma unroll
    for (int s = 128; s > 0; s >>= 1) {
        if (n < s) s_red[n] = fmaxf(s_red[n], s_red[n + s]);
        __syncthreads();
    }
    float m = s_red[0];
    __syncthreads();
    float e = expf(feat - m);
    s_red[n] = e;
    __syncthreads();
#pragma unroll
    for (int s = 128; s > 0; s >>= 1) {
        if (n < s) s_red[n] += s_red[n + s];
        __syncthreads();
    }
    s_a[n] = e / s_red[0];
    __syncthreads();

    {
        float* ob = out_attn + (size_t)b * TT * NN;
#pragma unroll 4
        for (int i = tid; i < TT * NN / 4; i += 256) {
            int t = i >> 6, n4 = (i & 63) * 4;
            *(float4*)&ob[(size_t)t * NN + n4] = *(const float4*)&s_a[n4];
        }
    }

    // build A = fp16(a * x)
#pragma unroll
    for (int it = 0; it < 16; it++) {
        int seg = tid + 256 * it;
        int t = seg >> 5;
        int k8 = (seg & 31) * 8;
        float4 x0 = *(const float4*)&xb[(size_t)t * NN + k8];
        float4 x1 = *(const float4*)&xb[(size_t)t * NN + k8 + 4];
        float4 a0 = *(const float4*)&s_a[k8];
        float4 a1 = *(const float4*)&s_a[k8 + 4];
        float v[8] = {x0.x * a0.x, x0.y * a0.y, x0.z * a0.z, x0.w * a0.w,
                      x1.x * a1.x, x1.y * a1.y, x1.z * a1.z, x1.w * a1.w};
        u32 hw[4];
#pragma unroll
        for (int p = 0; p < 4; p++) {
            __half2 hp = __halves2half2(__float2half_rn(v[2 * p]),
                                        __float2half_rn(v[2 * p + 1]));
            hw[p] = *(u32*)&hp;
        }
        *(uint4*)&As[t * AP + k8] = make_uint4(hw[0], hw[1], hw[2], hw[3]);
    }

    int jseg = tid >> 3, kl8 = (tid & 7) * 8;
    uint4 rb[4];
#pragma unroll
    for (int it = 0; it < 4; it++) {
        int j = jseg + 32 * it;
        rb[it] = *(const uint4*)&g_wh[(size_t)j * NN + kl8];
    }

    int m0 = (wid >> 1) * 32;
    int n0 = (wid & 1) * 64;

    __syncthreads();

    int cc = 0;
    for (int jt = 0; jt < 4; jt++) {
        wmma::fragment<wmma::accumulator, 16, 16, 16, float> acc[2][4];
#pragma unroll
        for (int i = 0; i < 2; i++)
#pragma unroll
            for (int nn = 0; nn < 4; nn++) wmma::fill_fragment(acc[i][nn], 0.0f);

        for (int c = 0; c < 4; c++, cc++) {
            __half* Bc = Bs + (cc & 1) * 128 * BP;
#pragma unroll
            for (int it = 0; it < 4; it++) {
                int j = jseg + 32 * it;
                *(uint4*)&Bc[j * BP + kl8] = rb[it];
            }
            __syncthreads();

            if (cc < 15) {
                int njt = (cc + 1) >> 2, nc = (cc + 1) & 3;
#pragma unroll
                for (int it = 0; it < 4; it++) {
                    int j = jseg + 32 * it;
                    rb[it] = *(const uint4*)
                        &g_wh[(size_t)(njt * 128 + j) * NN + nc * 64 + kl8];
                }
            }

            int a_off = c * 64;
#pragma unroll
            for (int ks = 0; ks < 4; ks++) {
                wmma::fragment<wmma::matrix_a, 16, 16, 16, __half, wmma::row_major> af[2];
#pragma unroll
                for (int i = 0; i < 2; i++)
                    wmma::load_matrix_sync(af[i], &As[(m0 + i * 16) * AP + a_off + ks * 16], AP);
#pragma unroll
                for (int nn = 0; nn < 4; nn++) {
                    wmma::fragment<wmma::matrix_b, 16, 16, 16, __half, wmma::col_major> bf;
                    wmma::load_matrix_sync(bf, &Bc[(n0 + nn * 16) * BP + ks * 16], BP);
                    wmma::mma_sync(acc[0][nn], af[0], bf, acc[0][nn]);
                    wmma::mma_sync(acc[1][nn], af[1], bf, acc[1][nn]);
                }
            }
        }

#pragma unroll
        for (int i = 0; i < 2; i++)
#pragma unroll
            for (int nn = 0; nn < 4; nn++)
                wmma::store_matrix_sync(
                    xp + ((size_t)b * TT + m0 + i * 16) * GG + jt * 128 + n0 + nn * 16,
                    acc[i][nn], GG, wmma::mem_row_major);
    }
}

// ---------------------------------------------------------------------------
// Recurrent LSTM via wmma (exact R13 structure, fp16 dtype):
//  - B (w_hh fp16) fragments in registers for all 128 steps
//  - warp w owns columns {g*128 + w*16 .. +16} for all 4 gates; epilogue
//    warp-local (per-warp acc slab + __syncwarp)
//  - A tile (h hi/lo rows) double-buffered -> ONE __syncthreads per step
// ---------------------------------------------------------------------------
__global__ __launch_bounds__(256, 1)
void lstm_wmma_kernel(const float* __restrict__ xp,
                      const float* __restrict__ h0,
                      const float* __restrict__ c0,
                      float* __restrict__ out_enc) {
    __shared__ __half As[2][16 * APL];
    __shared__ float s_acc[8][16 * ACW];
    __shared__ float s_bias[GG];

    int tid = threadIdx.x;
    int wid = tid >> 5;
    int lane = tid & 31;
    int b0 = blockIdx.x * BM;

    wmma::fragment<wmma::matrix_b, 16, 16, 16, __half, wmma::col_major> bf[4][8];
#pragma unroll
    for (int g = 0; g < 4; g++)
#pragma unroll
        for (int ks = 0; ks < 8; ks++)
            wmma::load_matrix_sync(bf[g][ks],
                g_whhh + (size_t)(g * 128 + wid * 16) * HH + ks * 16, HH);

    for (int i = tid; i < GG; i += 256) s_bias[i] = g_bias[i];

    for (int i = tid; i < 2 * (APL / 4); i += 256) {
        int row = (i < APL / 4) ? 7 : 15;
        int col = (i % (APL / 4)) * 4;
        *(ull*)&As[0][row * APL + col] = 0ULL;
        *(ull*)&As[1][row * APL + col] = 0ULL;
    }

    const int er = lane >> 2;
    const int kq = (lane & 3) * 4;
    const int kk = wid * 16 + kq;
    const bool eact = lane < 28;
    const bool ewr  = eact && (b0 + er < BB);

    float c_reg[4] = {0.f, 0.f, 0.f, 0.f};
    if (eact) {
        float4 hv = make_float4(0.f, 0.f, 0.f, 0.f);
        if (ewr) {
            hv = *(const float4*)&h0[(size_t)(b0 + er) * HH + kk];
            float4 cv = *(const float4*)&c0[(size_t)(b0 + er) * HH + kk];
            c_reg[0] = cv.x; c_reg[1] = cv.y; c_reg[2] = cv.z; c_reg[3] = cv.w;
        }
        ull hi = pack_h4(hv.x, hv.y, hv.z, hv.w);
        float r0 = hv.x - __half2float(__float2half_rn(hv.x));
        float r1 = hv.y - __half2float(__float2half_rn(hv.y));
        float r2 = hv.z - __half2float(__float2half_rn(hv.z));
        float r3 = hv.w - __half2float(__float2half_rn(hv.w));
        ull lo = pack_h4(r0, r1, r2, r3);
        *(ull*)&As[0][er * APL + kk]       = hi;
        *(ull*)&As[0][(er + 8) * APL + kk] = lo;
    }

    int bclamp = b0 + er; if (bclamp > BB - 1) bclamp = BB - 1;
    const float* xrow_e = xp + (size_t)bclamp * TT * GG;
    float* accw = &s_acc[wid][0];

    __syncthreads();

    for (int t = 0; t < TT; t++) {
        int cur = t & 1, nxt = cur ^ 1;

        float4 xpv[4];
        if (eact) {
#pragma unroll
            for (int g = 0; g < 4; g++)
                xpv[g] = *(const float4*)&xrow_e[(size_t)t * GG + g * 128 + kk];
        }

        wmma::fragment<wmma::accumulator, 16, 16, 16, float> acc[4];
#pragma unroll
        for (int g = 0; g < 4; g++) wmma::fill_fragment(acc[g], 0.0f);
#pragma unroll
        for (int ks = 0; ks < 8; ks++) {
            wmma::fragment<wmma::matrix_a, 16, 16, 16, __half, wmma::row_major> af;
            wmma::load_matrix_sync(af, &As[cur][ks * 16], APL);
#pragma unroll
            for (int g = 0; g < 4; g++)
                wmma::mma_sync(acc[g], af, bf[g][ks], acc[g]);
        }
#pragma unroll
        for (int g = 0; g < 4; g++)
            wmma::store_matrix_sync(&accw[g * 16], acc[g], ACW, wmma::mem_row_major);
        __syncwarp();

        if (eact) {
            float gate[4][4];
#pragma unroll
            for (int g = 0; g < 4; g++) {
                float4 ahi = *(const float4*)&accw[er * ACW + g * 16 + kq];
                float4 alo = *(const float4*)&accw[(er + 8) * ACW + g * 16 + kq];
                float4 bg  = *(const float4*)&s_bias[g * 128 + kk];
                gate[g][0] = ahi.x + alo.x + bg.x + xpv[g].x;
                gate[g][1] = ahi.y + alo.y + bg.y + xpv[g].y;
                gate[g][2] = ahi.z + alo.z + bg.z + xpv[g].z;
                gate[g][3] = ahi.w + alo.w + bg.w + xpv[g].w;
            }
            float hn[4];
#pragma unroll
            for (int l = 0; l < 4; l++) {
                float iv = fsig(gate[0][l]);
                float fv = fsig(gate[1][l]);
                float gv = ftanh(gate[2][l]);
                float ov = fsig(gate[3][l]);
                c_reg[l] = fmaf(fv, c_reg[l], iv * gv);
                hn[l] = ov * ftanh(c_reg[l]);
            }
            ull hi = pack_h4(hn[0], hn[1], hn[2], hn[3]);
            float r0 = hn[0] - __half2float(__float2half_rn(hn[0]));
            float r1 = hn[1] - __half2float(__float2half_rn(hn[1]));
            float r2 = hn[2] - __half2float(__float2half_rn(hn[2]));
            float r3 = hn[3] - __half2float(__float2half_rn(hn[3]));
            ull lo = pack_h4(r0, r1, r2, r3);
            *(ull*)&As[nxt][er * APL + kk]       = hi;
            *(ull*)&As[nxt][(er + 8) * APL + kk] = lo;
            if (ewr)
                *(float4*)(out_enc + ((size_t)(b0 + er) * TT + t) * HH + kk) =
                    make_float4(hn[0], hn[1], hn[2], hn[3]);
        }
        __syncthreads();
    }
}

// ---------------------------------------------------------------------------
// Launch
// ---------------------------------------------------------------------------
extern "C" void kernel_launch(void* const* d_in, const int* in_sizes, int n_in,
                              void* d_out, int out_size) {
    const float* x      = (const float*)d_in[0];
    const float* attn_w = (const float*)d_in[1];
    const float* attn_b = (const float*)d_in[2];
    const float* w_ih   = (const float*)d_in[3];
    const float* w_hh   = (const float*)d_in[4];
    const float* b_ih   = (const float*)d_in[5];
    const float* b_hh   = (const float*)d_in[6];
    const float* h0     = (const float*)d_in[7];
    const float* c0     = (const float*)d_in[8];

    float* out      = (float*)d_out;
    float* out_attn = out;
    float* out_enc  = out + (size_t)BB * TT * NN;

    float* xproj;
    cudaGetSymbolAddress((void**)&xproj, g_xproj);

    cudaFuncSetAttribute(fused_attn_xproj_kernel,
                         cudaFuncAttributeMaxDynamicSharedMemorySize, XP_SMEM);

    setup_kernel<<<192, 256>>>(w_ih, w_hh, b_ih, b_hh);
    fused_attn_xproj_kernel<<<BB, 256, XP_SMEM>>>(x, attn_w, attn_b, out_attn, xproj);
    lstm_wmma_kernel<<<NBLK, 256>>>(xproj, h0, c0, out_enc);
}